// round 14
// baseline (speedup 1.0000x reference)
#include <cuda_runtime.h>

#define NNODES 4096
#define MASK_WORDS 128   // 4096/32
#define NGRAPH 64
#define MAXNBR 320       // binomial(4096,0.02): mean 82, sigma 9 (clamped defensively)

// ---------------- scratch (no allocations allowed) ----------------
__device__ float          g_f[NNODES * 64];       // per-layer head features [N][64]
__device__ float          g_s1[2 * NNODES];       // s1: [head][row] planar
__device__ float          g_s2[2 * NNODES];       // s2: [head][row] planar
__device__ unsigned short g_nbr[NNODES * MAXNBR]; // CSR neighbor lists (built layer 1)
__device__ int            g_cnt[NNODES];          // CSR counts
__device__ float          g_h[NNODES * 192];      // concat(x1,x2,x3)

// ---------------- K1: f = X @ Wcat + bcat, fused s1/s2 epilogue ----------------
// 16-row x 64-col tiles, 128 threads, register-prefetch pipeline. grid = 256.
// W layout: [2][K][32] (head, k, feat). Output g_f[row][head*32+feat].
__global__ void __launch_bounds__(128) gemm_f(
        const float* __restrict__ Xext, int use_h, int hcol,
        int ldx, int K,
        const float* __restrict__ W, const float* __restrict__ b,
        const float* __restrict__ a1w, const float* __restrict__ a1b,
        const float* __restrict__ a2w, const float* __restrict__ a2b) {
    __shared__ float As[16][33];
    __shared__ float Bs[32][64];
    const float* X = use_h ? (g_h + hcol) : Xext;
    int t = threadIdx.x;             // 128 threads
    int row0 = blockIdx.x * 16;
    int tx = t & 15, ty = t >> 4;    // tx: 16 col-groups of 4, ty: 8 row-pairs

    float acc[2][4] = {};
    float aR[4];
    float4 bR[4];

    const int KT = K >> 5;

    #pragma unroll
    for (int i = 0; i < 4; i++) {
        int idx = t + i * 128;
        aR[i] = X[(size_t)(row0 + (idx >> 5)) * ldx + (idx & 31)];
        int kk = idx >> 4, f4g = idx & 15;
        int head = f4g >> 3, f4 = f4g & 7;
        bR[i] = *reinterpret_cast<const float4*>(&W[(size_t)(head * K + kk) * 32 + f4 * 4]);
    }

    for (int kt = 0; kt < KT; kt++) {
        __syncthreads();
        #pragma unroll
        for (int i = 0; i < 4; i++) {
            int idx = t + i * 128;
            As[idx >> 5][idx & 31] = aR[i];
            int kk = idx >> 4, f4g = idx & 15;
            reinterpret_cast<float4*>(&Bs[kk][0])[f4g] = bR[i];
        }
        __syncthreads();
        if (kt + 1 < KT) {
            int k0 = (kt + 1) << 5;
            #pragma unroll
            for (int i = 0; i < 4; i++) {
                int idx = t + i * 128;
                aR[i] = X[(size_t)(row0 + (idx >> 5)) * ldx + (k0 + (idx & 31))];
                int kk = idx >> 4, f4g = idx & 15;
                int head = f4g >> 3, f4 = f4g & 7;
                bR[i] = *reinterpret_cast<const float4*>(&W[(size_t)(head * K + k0 + kk) * 32 + f4 * 4]);
            }
        }
        #pragma unroll
        for (int kk = 0; kk < 32; kk++) {
            float a0 = As[ty * 2 + 0][kk];
            float a1 = As[ty * 2 + 1][kk];
            float4 bv = reinterpret_cast<const float4*>(&Bs[kk][0])[tx];
            acc[0][0] += a0 * bv.x; acc[0][1] += a0 * bv.y;
            acc[0][2] += a0 * bv.z; acc[0][3] += a0 * bv.w;
            acc[1][0] += a1 * bv.x; acc[1][1] += a1 * bv.y;
            acc[1][2] += a1 * bv.z; acc[1][3] += a1 * bv.w;
        }
    }

    float p1[2] = {0.f, 0.f}, p2[2] = {0.f, 0.f};
    #pragma unroll
    for (int rr = 0; rr < 2; rr++) {
        #pragma unroll
        for (int j = 0; j < 4; j++) {
            int n = (tx << 2) + j;
            float v = acc[rr][j] + b[n];
            g_f[(size_t)(row0 + ty * 2 + rr) * 64 + n] = v;
            p1[rr] += v * a1w[n];
            p2[rr] += v * a2w[n];
        }
    }
    #pragma unroll
    for (int o = 1; o < 8; o <<= 1) {
        p1[0] += __shfl_xor_sync(0xffffffffu, p1[0], o);
        p1[1] += __shfl_xor_sync(0xffffffffu, p1[1], o);
        p2[0] += __shfl_xor_sync(0xffffffffu, p2[0], o);
        p2[1] += __shfl_xor_sync(0xffffffffu, p2[1], o);
    }
    if ((tx & 7) == 0) {
        int head = tx >> 3;
        int r0 = row0 + ty * 2;
        g_s1[head * NNODES + r0]     = p1[0] + a1b[head];
        g_s1[head * NNODES + r0 + 1] = p1[1] + a1b[head];
        g_s2[head * NNODES + r0]     = p2[0] + a2b[head];
        g_s2[head * NNODES + r0 + 1] = p2[1] + a2b[head];
    }
}

// ---------------- attention body: ONE WARP handles (row, head). No barriers. ----------------
// lane k owns feature k of this head. s_idx/s_e shared per row slot in the CTA.
__device__ __forceinline__ void attn_head_body(const unsigned short* s_idx, float* s_e,
                                               int lane, int head, int row, int cnt,
                                               int hoff) {
    const float* s2p = &g_s2[head * NNODES];

    // Phase B: logits (leaky relu) + warp max
    float s1v = g_s1[head * NNODES + row];
    float mx = -1e30f;
    for (int t = lane; t < cnt; t += 32) {
        float e = s1v + s2p[s_idx[t]];
        e = e > 0.f ? e : 0.01f * e;
        s_e[t] = e;
        mx = fmaxf(mx, e);
    }
    #pragma unroll
    for (int o = 16; o; o >>= 1)
        mx = fmaxf(mx, __shfl_xor_sync(0xffffffffu, mx, o));

    // Phase C: exp + warp sum
    float sum = 0.f;
    for (int t = lane; t < cnt; t += 32) {
        float w = __expf(s_e[t] - mx);
        s_e[t] = w;
        sum += w;
    }
    #pragma unroll
    for (int o = 16; o; o >>= 1)
        sum += __shfl_xor_sync(0xffffffffu, sum, o);
    float inv = 1.f / sum;
    __syncwarp();

    // Phase D: lane k accumulates feature head*32+k over all neighbors
    const float* fbase = g_f + head * 32 + lane;
    float acc = 0.f;
    #pragma unroll 4
    for (int t = 0; t < cnt; t++) {
        acc += s_e[t] * fbase[(size_t)s_idx[t] * 64];
    }
    float o = acc * inv;
    g_h[(size_t)row * 192 + hoff + head * 32 + lane] = o > 0.f ? o : 0.f;
}

// ---------------- K2a: layer-1 attention, builds CSR from adj (DRAM read) ----------------
// CTA = 128 thr = 4 warps = 2 rows x 2 heads. r = wp>>1, head = wp&1.
__global__ void __launch_bounds__(128) attn_build(const float* __restrict__ adj) {
    __shared__ unsigned s_words[2][MASK_WORDS];  // 1 KB
    __shared__ unsigned short s_idx[2][MAXNBR];  // 1.25 KB
    __shared__ float s_e[2][2][MAXNBR];          // [row][head] 5 KB
    __shared__ int s_cnt[2];

    int tid = threadIdx.x, wp = tid >> 5, lane = tid & 31;
    int r = wp >> 1, half = wp & 1;              // during build: half = which half of the row read
    int row = blockIdx.x * 2 + r;

    // Phase A0: each row's 16 KB adj read split across its warp pair
    const float4* arow = reinterpret_cast<const float4*>(adj + (size_t)row * NNODES);
    #pragma unroll 4
    for (int g = half * 16; g < half * 16 + 16; g++) {
        float4 v = arow[g * 32 + lane];
        unsigned b0 = __ballot_sync(0xffffffffu, v.x > 0.0f);
        unsigned b1 = __ballot_sync(0xffffffffu, v.y > 0.0f);
        unsigned b2 = __ballot_sync(0xffffffffu, v.z > 0.0f);
        unsigned b3 = __ballot_sync(0xffffffffu, v.w > 0.0f);
        if (lane < 4) {
            int sh = lane * 8;
            unsigned n0 = (b0 >> sh) & 0xffu;
            unsigned n1 = (b1 >> sh) & 0xffu;
            unsigned n2 = (b2 >> sh) & 0xffu;
            unsigned n3 = (b3 >> sh) & 0xffu;
            unsigned w = 0;
            #pragma unroll
            for (int i = 0; i < 8; i++) {
                w |= ((n0 >> i) & 1u) << (i * 4 + 0);
                w |= ((n1 >> i) & 1u) << (i * 4 + 1);
                w |= ((n2 >> i) & 1u) << (i * 4 + 2);
                w |= ((n3 >> i) & 1u) << (i * 4 + 3);
            }
            s_words[r][g * 4 + lane] = w;
        }
    }
    __syncthreads();

    // Phase A1: warps 0 and 2 extract their row's indices (warp-local scan)
    if (half == 0) {
        unsigned m[4];
        int c = 0;
        #pragma unroll
        for (int i = 0; i < 4; i++) { m[i] = s_words[r][lane * 4 + i]; c += __popc(m[i]); }
        int inc = c;
        #pragma unroll
        for (int o = 1; o < 32; o <<= 1) {
            int n = __shfl_up_sync(0xffffffffu, inc, o);
            if (lane >= o) inc += n;
        }
        int cw = __shfl_sync(0xffffffffu, inc, 31);
        int pos = inc - c;
        #pragma unroll
        for (int i = 0; i < 4; i++) {
            unsigned mm = m[i];
            int base = (lane * 4 + i) * 32;
            while (mm) {
                int bp = __ffs(mm) - 1; mm &= mm - 1;
                if (pos < MAXNBR) s_idx[r][pos] = (unsigned short)(base + bp);
                pos++;
            }
        }
        if (lane == 0) s_cnt[r] = cw > MAXNBR ? MAXNBR : cw;
    }
    __syncthreads();
    int cnt = s_cnt[r];

    // persist CSR for layers 2/3 (each row's warp pair splits the write)
    for (int t = half * 32 + lane; t < cnt; t += 64)
        g_nbr[(size_t)row * MAXNBR + t] = s_idx[r][t];
    if (tid == 0) g_cnt[row]     = s_cnt[0];
    if (tid == 1) g_cnt[row + 1] = s_cnt[1];

    // per-(row, head) body, fully independent warps
    attn_head_body(s_idx[r], s_e[r][half], lane, half, row, cnt, 0);
}

// ---------------- K2b: layers 2/3 attention (reads CSR) ----------------
__global__ void __launch_bounds__(128) attn_kernel(int hoff) {
    __shared__ unsigned short s_idx[2][MAXNBR];
    __shared__ float s_e[2][2][MAXNBR];
    __shared__ int s_cnt[2];

    int tid = threadIdx.x, wp = tid >> 5, lane = tid & 31;
    int r = wp >> 1, head = wp & 1;
    int row = blockIdx.x * 2 + r;

    if (tid < 2) s_cnt[tid] = g_cnt[blockIdx.x * 2 + tid];
    __syncthreads();
    int cnt = s_cnt[r];
    for (int t = head * 32 + lane; t < cnt; t += 64)
        s_idx[r][t] = g_nbr[(size_t)row * MAXNBR + t];
    __syncthreads();

    attn_head_body(s_idx[r], s_e[r][head], lane, head, row, cnt, hoff);
}

// ---------------- K3: segment-mean pool + classifier + softmax ----------------
__global__ void final_kernel(const int* __restrict__ batch,
                             const float* __restrict__ Wf,
                             const float* __restrict__ bf,
                             float* __restrict__ out) {
    __shared__ float s_pool[192];
    __shared__ float s_log[10];
    int g = blockIdx.x;
    int tid = threadIdx.x;  // 192

    int lo = 0, hi = NNODES;
    while (lo < hi) { int mid = (lo + hi) >> 1; if (batch[mid] < g) lo = mid + 1; else hi = mid; }
    int start = lo;
    lo = start; hi = NNODES;
    while (lo < hi) { int mid = (lo + hi) >> 1; if (batch[mid] < g + 1) lo = mid + 1; else hi = mid; }
    int end = lo;
    int cnt = end - start;

    float sum = 0.f;
    for (int r = start; r < end; r++) sum += g_h[(size_t)r * 192 + tid];
    s_pool[tid] = sum / (float)(cnt > 0 ? cnt : 1);
    __syncthreads();

    if (tid < 10) {
        float l = bf[tid];
        for (int c = 0; c < 192; c++) l += s_pool[c] * Wf[c * 10 + tid];
        s_log[tid] = l;
    }
    __syncthreads();
    if (tid == 0) {
        float m = -1e30f;
        for (int o = 0; o < 10; o++) m = fmaxf(m, s_log[o]);
        float e[10], s = 0.f;
        for (int o = 0; o < 10; o++) { e[o] = __expf(s_log[o] - m); s += e[o]; }
        float inv = 1.f / s;
        for (int o = 0; o < 10; o++) out[g * 10 + o] = e[o] * inv;
    }
}

// ---------------- launch ----------------
extern "C" void kernel_launch(void* const* d_in, const int* in_sizes, int n_in,
                              void* d_out, int out_size) {
    const float* x   = (const float*)d_in[0];
    const float* adj = (const float*)d_in[1];
    const int* batch = (const int*)d_in[2];
    const float* W[3]   = {(const float*)d_in[3],  (const float*)d_in[9],  (const float*)d_in[15]};
    const float* b[3]   = {(const float*)d_in[4],  (const float*)d_in[10], (const float*)d_in[16]};
    const float* a1w[3] = {(const float*)d_in[5],  (const float*)d_in[11], (const float*)d_in[17]};
    const float* a1b[3] = {(const float*)d_in[6],  (const float*)d_in[12], (const float*)d_in[18]};
    const float* a2w[3] = {(const float*)d_in[7],  (const float*)d_in[13], (const float*)d_in[19]};
    const float* a2b[3] = {(const float*)d_in[8],  (const float*)d_in[14], (const float*)d_in[20]};
    const float* Wf = (const float*)d_in[21];
    const float* bf = (const float*)d_in[22];
    float* out = (float*)d_out;

    for (int L = 0; L < 3; L++) {
        int K    = (L == 0) ? 512 : 64;
        int useh = (L == 0) ? 0 : 1;
        int hcol = (L == 0) ? 0 : (L - 1) * 64;
        int ldx  = (L == 0) ? 512 : 192;
        gemm_f<<<NNODES / 16, 128>>>(x, useh, hcol, ldx, K, W[L], b[L],
                                     a1w[L], a1b[L], a2w[L], a2b[L]);
        if (L == 0) attn_build<<<NNODES / 2, 128>>>(adj);
        else        attn_kernel<<<NNODES / 2, 128>>>(L * 64);
    }

    final_kernel<<<NGRAPH, 192>>>(batch, Wf, bf, out);
}